// round 4
// baseline (speedup 1.0000x reference)
#include <cuda_runtime.h>
#include <cuda_fp16.h>
#include <cstdint>

// Input [32, 512, 512, 3] float32 NHWC, 3x3 median, replicate border.
constexpr int Bn  = 32;
constexpr int H   = 512;
constexpr int W   = 512;
constexpr int C   = 3;
constexpr int ROW = W * C;             // 1536 floats per image row
constexpr int IMG = H * ROW;
constexpr int EPT = 8;                 // wc outputs per thread per row
constexpr int TPR = ROW / EPT;         // 192
constexpr int PPT = 4;                 // row-pairs per thread (8 output rows)
constexpr int GROUPS = (H / 2) / PPT;  // 64 pair-groups per image
constexpr int NTH = Bn * GROUPS * TPR; // 393,216 threads
constexpr int BLOCK = 256;

__device__ __forceinline__ __half2 med3h2(__half2 a, __half2 b, __half2 c) {
    __half2 mn = __hmin2(a, b);
    __half2 mx = __hmax2(a, b);
    return __hmax2(mn, __hmin2(mx, c));
}
// (a.high16 | b.low16) — one PRMT
__device__ __forceinline__ __half2 prmt_h2(__half2 a, __half2 b) {
    unsigned int au = *reinterpret_cast<unsigned int*>(&a);
    unsigned int bu = *reinterpret_cast<unsigned int*>(&b);
    unsigned int r  = __byte_perm(au, bu, 0x5432);
    return *reinterpret_cast<__half2*>(&r);
}

// Load 16-float horizontal window with replicate remap at image edges done in
// registers (loads always vectorized & aligned).
// mode 0: interior, base = wc0-4   ; mode 1: wc0==0, base=0 ; mode 2: wc0==ROW-8, base=ROW-16
__device__ __forceinline__ void load_win(const float* __restrict__ r, int base,
                                         int mode, float w[16]) {
    const float4* p = reinterpret_cast<const float4*>(r + base);
    float4 t0 = p[0], t1 = p[1], t2 = p[2], t3 = p[3];
    float t[16] = {t0.x, t0.y, t0.z, t0.w, t1.x, t1.y, t1.z, t1.w,
                   t2.x, t2.y, t2.z, t2.w, t3.x, t3.y, t3.z, t3.w};
    if (mode == 0) {
        #pragma unroll
        for (int k = 0; k < 16; k++) w[k] = t[k];
    } else if (mode == 1) {
        w[0] = t[0]; w[1] = t[0]; w[2] = t[1]; w[3] = t[2];
        #pragma unroll
        for (int k = 4; k < 16; k++) w[k] = t[k - 4];
    } else {
        #pragma unroll
        for (int k = 0; k < 12; k++) w[k] = t[k + 4];
        w[12] = t[13]; w[13] = t[14]; w[14] = t[15]; w[15] = t[15];
    }
}

// Column sorts + pair-shared horizontal combine + store of one packed row pair.
__device__ __forceinline__ void process_store(const __half2* x, const __half2* y,
                                              const __half2* z, float* o) {
    __half2 mn[15], md[15], mx[15];
    #pragma unroll
    for (int k = 1; k <= 14; k++) {
        __half2 lo2 = __hmin2(y[k], z[k]);
        __half2 hi2 = __hmax2(y[k], z[k]);
        mn[k] = __hmin2(x[k], lo2);
        mx[k] = __hmax2(x[k], hi2);
        md[k] = __hmax2(lo2, __hmin2(x[k], hi2));
    }
    // Shared pair reductions Q_k over columns (k, k+3), k = 4..8.
    // Outputs j<4 use Q_{j+4} + single col j+1; j>=4 use Q_{j+1} + single col j+7.
    __half2 qlo[9], qhi[9], qa[9], qb[9];
    #pragma unroll
    for (int k = 4; k <= 8; k++) {
        qlo[k] = __hmax2(mn[k], mn[k + 3]);
        qhi[k] = __hmin2(mx[k], mx[k + 3]);
        qa[k]  = __hmin2(md[k], md[k + 3]);
        qb[k]  = __hmax2(md[k], md[k + 3]);
    }
    float r0[EPT], r1[EPT];
    #pragma unroll
    for (int j = 0; j < EPT; j++) {
        int kp = (j < 4) ? (j + 4) : (j + 1);   // pair index
        int ks = (j < 4) ? (j + 1) : (j + 7);   // single column
        __half2 lo = __hmax2(qlo[kp], mn[ks]);
        __half2 hi = __hmin2(qhi[kp], mx[ks]);
        __half2 mi = __hmax2(qa[kp], __hmin2(md[ks], qb[kp]));  // med3 of mds
        __half2 m  = med3h2(lo, mi, hi);
        float2 f = __half22float2(m);
        r0[j] = f.x;
        r1[j] = f.y;
    }
    float4* po0 = reinterpret_cast<float4*>(o);
    float4* po1 = reinterpret_cast<float4*>(o + ROW);
    po0[0] = make_float4(r0[0], r0[1], r0[2], r0[3]);
    po0[1] = make_float4(r0[4], r0[5], r0[6], r0[7]);
    po1[0] = make_float4(r1[0], r1[1], r1[2], r1[3]);
    po1[1] = make_float4(r1[4], r1[5], r1[6], r1[7]);
}

__global__ void __launch_bounds__(BLOCK, 3)
median3x3_march3_kernel(const float* __restrict__ in, float* __restrict__ out) {
    int tid = blockIdx.x * BLOCK + threadIdx.x;
    int wc0  = (tid % TPR) * EPT;
    int rest = tid / TPR;
    int g    = rest % GROUPS;
    int b    = rest / GROUPS;
    int h0   = g * (2 * PPT);

    int mode = (wc0 == 0) ? 1 : ((wc0 == ROW - EPT) ? 2 : 0);
    int base = (mode == 0) ? (wc0 - 4) : ((mode == 1) ? 0 : (ROW - 16));

    const float* img = in + (int64_t)b * IMG;
    float* o = out + (int64_t)b * IMG + (int64_t)h0 * ROW + wc0;

    // ---- prologue: build x,y,z incrementally (peak 2 float windows live) ----
    __half2 x[15], y[15], z[15];
    {
        float wa[16], wb[16];
        load_win(img + (int64_t)max(h0 - 1, 0) * ROW, base, mode, wa);
        load_win(img + (int64_t)h0 * ROW,             base, mode, wb);
        #pragma unroll
        for (int k = 1; k <= 14; k++) x[k] = __floats2half2_rn(wa[k], wb[k]);  // (h-1|h)
        load_win(img + (int64_t)(h0 + 1) * ROW, base, mode, wa);               // row h+1
        #pragma unroll
        for (int k = 1; k <= 14; k++) y[k] = __floats2half2_rn(wb[k], wa[k]);  // (h|h+1)
        load_win(img + (int64_t)(h0 + 2) * ROW, base, mode, wb);               // row h+2
        #pragma unroll
        for (int k = 1; k <= 14; k++) z[k] = __floats2half2_rn(wa[k], wb[k]);  // (h+1|h+2)
    }
    process_store(x, y, z, o);
    o += 2 * ROW;

    // ---- march: pairs (h, h+1), h = h0+2i; carry z as the new x ----
    #pragma unroll
    for (int i = 1; i < PPT; i++) {
        int h = h0 + 2 * i;
        float w1[16], w2[16];
        load_win(img + (int64_t)(h + 1) * ROW,           base, mode, w1);
        load_win(img + (int64_t)min(h + 2, H - 1) * ROW, base, mode, w2);
        __half2 yn[15], zn[15];
        #pragma unroll
        for (int k = 1; k <= 14; k++) {
            zn[k] = __floats2half2_rn(w1[k], w2[k]);   // (h+1 | h+2)
            yn[k] = prmt_h2(z[k], zn[k]);              // (h   | h+1)
        }
        process_store(z, yn, zn, o);
        #pragma unroll
        for (int k = 1; k <= 14; k++) z[k] = zn[k];
        o += 2 * ROW;
    }
}

extern "C" void kernel_launch(void* const* d_in, const int* in_sizes, int n_in,
                              void* d_out, int out_size) {
    const float* in = (const float*)d_in[0];
    float* out = (float*)d_out;
    int blocks = NTH / BLOCK;   // 1536
    median3x3_march3_kernel<<<blocks, BLOCK>>>(in, out);
}

// round 5
// speedup vs baseline: 1.0490x; 1.0490x over previous
#include <cuda_runtime.h>
#include <cuda_fp16.h>
#include <cstdint>

// Input [32, 512, 512, 3] float32 NHWC, 3x3 median, replicate border.
constexpr int Bn  = 32;
constexpr int H   = 512;
constexpr int W   = 512;
constexpr int C   = 3;
constexpr int ROW = W * C;             // 1536 floats per image row
constexpr int IMG = H * ROW;
constexpr int EPT = 8;                 // wc outputs per thread per row
constexpr int TPR = ROW / EPT;         // 192
constexpr int PPT = 8;                 // row-pairs per thread (16 output rows)
constexpr int GROUPS = (H / 2) / PPT;  // 32 pair-groups per image
constexpr int NTH = Bn * GROUPS * TPR; // 196,608 threads
constexpr int BLOCK = 256;

__device__ __forceinline__ __half2 med3h2(__half2 a, __half2 b, __half2 c) {
    __half2 mn = __hmin2(a, b);
    __half2 mx = __hmax2(a, b);
    return __hmax2(mn, __hmin2(mx, c));
}
// (a.high16 | b.low16) — one PRMT
__device__ __forceinline__ __half2 prmt_h2(__half2 a, __half2 b) {
    unsigned int au = *reinterpret_cast<unsigned int*>(&a);
    unsigned int bu = *reinterpret_cast<unsigned int*>(&b);
    unsigned int r  = __byte_perm(au, bu, 0x5432);
    return *reinterpret_cast<__half2*>(&r);
}

// Load 16-float horizontal window with replicate remap at image edges done in
// registers (loads always vectorized & aligned).
// mode 0: interior, base = wc0-4 ; mode 1: wc0==0, base=0 ; mode 2: wc0==ROW-8, base=ROW-16
__device__ __forceinline__ void load_win(const float* __restrict__ r, int base,
                                         int mode, float w[16]) {
    const float4* p = reinterpret_cast<const float4*>(r + base);
    float4 t0 = p[0], t1 = p[1], t2 = p[2], t3 = p[3];
    float t[16] = {t0.x, t0.y, t0.z, t0.w, t1.x, t1.y, t1.z, t1.w,
                   t2.x, t2.y, t2.z, t2.w, t3.x, t3.y, t3.z, t3.w};
    if (mode == 0) {
        #pragma unroll
        for (int k = 0; k < 16; k++) w[k] = t[k];
    } else if (mode == 1) {
        w[0] = t[0]; w[1] = t[0]; w[2] = t[1]; w[3] = t[2];
        #pragma unroll
        for (int k = 4; k < 16; k++) w[k] = t[k - 4];
    } else {
        #pragma unroll
        for (int k = 0; k < 12; k++) w[k] = t[k + 4];
        w[12] = t[13]; w[13] = t[14]; w[14] = t[15]; w[15] = t[15];
    }
}

// Column sorts + pair-shared horizontal combine + store of one packed row pair.
__device__ __forceinline__ void process_store(const __half2* x, const __half2* y,
                                              const __half2* z, float* o) {
    __half2 mn[15], md[15], mx[15];
    #pragma unroll
    for (int k = 1; k <= 14; k++) {
        __half2 lo2 = __hmin2(y[k], z[k]);
        __half2 hi2 = __hmax2(y[k], z[k]);
        mn[k] = __hmin2(x[k], lo2);
        mx[k] = __hmax2(x[k], hi2);
        md[k] = __hmax2(lo2, __hmin2(x[k], hi2));
    }
    // Shared pair reductions Q_k over columns (k, k+3), k = 4..8.
    // Outputs j<4 use Q_{j+4} + single col j+1; j>=4 use Q_{j+1} + single col j+7.
    __half2 qlo[9], qhi[9], qa[9], qb[9];
    #pragma unroll
    for (int k = 4; k <= 8; k++) {
        qlo[k] = __hmax2(mn[k], mn[k + 3]);
        qhi[k] = __hmin2(mx[k], mx[k + 3]);
        qa[k]  = __hmin2(md[k], md[k + 3]);
        qb[k]  = __hmax2(md[k], md[k + 3]);
    }
    float r0[EPT], r1[EPT];
    #pragma unroll
    for (int j = 0; j < EPT; j++) {
        int kp = (j < 4) ? (j + 4) : (j + 1);   // pair index
        int ks = (j < 4) ? (j + 1) : (j + 7);   // single column
        __half2 lo = __hmax2(qlo[kp], mn[ks]);
        __half2 hi = __hmin2(qhi[kp], mx[ks]);
        __half2 mi = __hmax2(qa[kp], __hmin2(md[ks], qb[kp]));  // med3 of mds
        __half2 m  = med3h2(lo, mi, hi);
        float2 f = __half22float2(m);
        r0[j] = f.x;
        r1[j] = f.y;
    }
    float4* po0 = reinterpret_cast<float4*>(o);
    float4* po1 = reinterpret_cast<float4*>(o + ROW);
    po0[0] = make_float4(r0[0], r0[1], r0[2], r0[3]);
    po0[1] = make_float4(r0[4], r0[5], r0[6], r0[7]);
    po1[0] = make_float4(r1[0], r1[1], r1[2], r1[3]);
    po1[1] = make_float4(r1[4], r1[5], r1[6], r1[7]);
}

__global__ void __launch_bounds__(BLOCK)
median3x3_deep_kernel(const float* __restrict__ in, float* __restrict__ out) {
    int tid = blockIdx.x * BLOCK + threadIdx.x;
    int wc0  = (tid % TPR) * EPT;
    int rest = tid / TPR;
    int g    = rest % GROUPS;
    int b    = rest / GROUPS;
    int h0   = g * (2 * PPT);

    int mode = (wc0 == 0) ? 1 : ((wc0 == ROW - EPT) ? 2 : 0);
    int base = (mode == 0) ? (wc0 - 4) : ((mode == 1) ? 0 : (ROW - 16));

    const float* img = in + (int64_t)b * IMG;
    float* o = out + (int64_t)b * IMG + (int64_t)h0 * ROW + wc0;

    // ---- prologue: build x,y,z incrementally (peak 2 float windows live) ----
    __half2 x[15], y[15], z[15];
    {
        float wa[16], wb[16];
        load_win(img + (int64_t)max(h0 - 1, 0) * ROW, base, mode, wa);
        load_win(img + (int64_t)h0 * ROW,             base, mode, wb);
        #pragma unroll
        for (int k = 1; k <= 14; k++) x[k] = __floats2half2_rn(wa[k], wb[k]);  // (h-1|h)
        load_win(img + (int64_t)(h0 + 1) * ROW, base, mode, wa);               // row h+1
        #pragma unroll
        for (int k = 1; k <= 14; k++) y[k] = __floats2half2_rn(wb[k], wa[k]);  // (h|h+1)
        load_win(img + (int64_t)(h0 + 2) * ROW, base, mode, wb);               // row h+2
        #pragma unroll
        for (int k = 1; k <= 14; k++) z[k] = __floats2half2_rn(wa[k], wb[k]);  // (h+1|h+2)
    }
    process_store(x, y, z, o);
    o += 2 * ROW;

    // ---- march: pairs (h, h+1), h = h0+2i; carry z as the new x ----
    #pragma unroll
    for (int i = 1; i < PPT; i++) {
        int h = h0 + 2 * i;
        float w1[16], w2[16];
        load_win(img + (int64_t)(h + 1) * ROW,           base, mode, w1);
        load_win(img + (int64_t)min(h + 2, H - 1) * ROW, base, mode, w2);
        __half2 yn[15], zn[15];
        #pragma unroll
        for (int k = 1; k <= 14; k++) {
            zn[k] = __floats2half2_rn(w1[k], w2[k]);   // (h+1 | h+2)
            yn[k] = prmt_h2(z[k], zn[k]);              // (h   | h+1)
        }
        process_store(z, yn, zn, o);
        #pragma unroll
        for (int k = 1; k <= 14; k++) z[k] = zn[k];
        o += 2 * ROW;
    }
}

extern "C" void kernel_launch(void* const* d_in, const int* in_sizes, int n_in,
                              void* d_out, int out_size) {
    const float* in = (const float*)d_in[0];
    float* out = (float*)d_out;
    int blocks = NTH / BLOCK;   // 768
    median3x3_deep_kernel<<<blocks, BLOCK>>>(in, out);
}